// round 14
// baseline (speedup 1.0000x reference)
#include <cuda_runtime.h>
#include <cuda_fp16.h>
#include <math_constants.h>

#define NN 100000
#define EE 3200000
#define GG 256
#define HH 16
#define CSR_CAP 3500032
#define SENT_ROW NN
#define NBLK 592
#define NTHR 256
#define TT (NBLK * NTHR)          // 151552 threads
#define CHUNK 169                 // ceil(NN/NBLK)
#define NBAR_PER_RUN 9ULL

__device__ int   d_cnt[NN];        // zeroed in g2 phase (static 0 first run)
__device__ float d_dis1[NN];
__device__ float d_dis2[NN];
__device__ int   d_off[NN];
__device__ __align__(16) unsigned short d_rank[EE];
__device__ int   d_bsum2[NBLK];
__device__ unsigned long long d_bar;   // monotonic grid-barrier counter
__device__ __align__(16) unsigned int d_csr[CSR_CAP];    // (row<<15)|w15
__device__ __align__(128) __half d_h1pre[(NN + 8) * HH];
__device__ __align__(128) __half d_h1[(NN + 8) * HH];
__device__ __align__(128) float  d_out2[NN * HH];
__device__ __align__(128) __half d_h2pre[(NN + 8) * HH];
__device__ float d_gmax[GG * HH];  // reset in mlp phase; relu>=0 so 0-seed valid

#define W_SCALE (1.0f / 32767.0f)

__device__ __forceinline__ void atomic_max_float(float* addr, float v) {
    if (v >= 0.0f) atomicMax((int*)addr, __float_as_int(v));
    else           atomicMin((unsigned int*)addr, __float_as_uint(v));
}

__device__ __forceinline__ void h8_to_f8(uint4 hv, float* o) {
    float2 f0 = __half22float2(*reinterpret_cast<__half2*>(&hv.x));
    float2 f1 = __half22float2(*reinterpret_cast<__half2*>(&hv.y));
    float2 f2 = __half22float2(*reinterpret_cast<__half2*>(&hv.z));
    float2 f3 = __half22float2(*reinterpret_cast<__half2*>(&hv.w));
    o[0] = f0.x; o[1] = f0.y; o[2] = f1.x; o[3] = f1.y;
    o[4] = f2.x; o[5] = f2.y; o[6] = f3.x; o[7] = f3.y;
}

__device__ __forceinline__ void fma_rec8(float* acc, unsigned int p,
                                         const uint4* __restrict__ hp, int qi) {
    int r = (int)(p >> 15);
    float w = (float)(p & 32767u) * W_SCALE;
    float v[8];
    h8_to_f8(hp[(r << 1) + qi], v);
#pragma unroll
    for (int m = 0; m < 8; m++) acc[m] = fmaf(w, v[m], acc[m]);
}

__device__ __forceinline__ void max_rec8(__half2* am, unsigned int p,
                                         const uint4* __restrict__ hp, int qi) {
    uint4 v = hp[((int)(p >> 15) << 1) + qi];
    __half2* vm = reinterpret_cast<__half2*>(&v);
    am[0] = __hmax2(am[0], vm[0]);
    am[1] = __hmax2(am[1], vm[1]);
    am[2] = __hmax2(am[2], vm[2]);
    am[3] = __hmax2(am[3], vm[3]);
}

__device__ __forceinline__ void sum_rec8(float* acc, unsigned int p,
                                         const uint4* __restrict__ hp, int qi) {
    float v[8];
    h8_to_f8(hp[((int)(p >> 15) << 1) + qi], v);
#pragma unroll
    for (int m = 0; m < 8; m++) acc[m] += v[m];
}

// Grid barrier: thread 0 arrives + spins; replay-safe monotone counter.
#define GBAR() do {                                                          \
    __syncthreads();                                                         \
    if (threadIdx.x == 0) {                                                  \
        __threadfence();                                                     \
        atomicAdd(&d_bar, 1ULL);                                             \
        tgt += (unsigned long long)NBLK;                                     \
        while (*(volatile unsigned long long*)&d_bar < tgt) __nanosleep(64); \
        __threadfence();                                                     \
    }                                                                        \
    __syncthreads();                                                         \
} while (0)

__global__ void __launch_bounds__(NTHR, 4) k_mega(
    const float* __restrict__ x, const int* __restrict__ row,
    const int* __restrict__ col, const int* __restrict__ batch,
    const float* __restrict__ w,
    const float* __restrict__ W1, const float* __restrict__ b1,
    const float* __restrict__ W2, const float* __restrict__ b2,
    const float* __restrict__ Wl1, const float* __restrict__ bl1,
    const float* __restrict__ Wl3, const float* __restrict__ bl3,
    const float* __restrict__ Wl4, const float* __restrict__ bl4,
    float* __restrict__ out)
{
    int tid = threadIdx.x;
    int gtid = blockIdx.x * NTHR + tid;
    unsigned long long tgt = 0;
    if (tid == 0) {
        unsigned long long v = *(volatile unsigned long long*)&d_bar;
        tgt = (v / (NBAR_PER_RUN * NBLK)) * (NBAR_PER_RUN * NBLK);
    }

    // ---- Phase 1: count + rank (4 edges/iter, grid-stride) ----
    for (int t = gtid; t < EE / 4; t += TT) {
        int4 c = reinterpret_cast<const int4*>(col)[t];
        unsigned short r0 = (unsigned short)atomicAdd(&d_cnt[c.x], 1);
        unsigned short r1 = (unsigned short)atomicAdd(&d_cnt[c.y], 1);
        unsigned short r2 = (unsigned short)atomicAdd(&d_cnt[c.z], 1);
        unsigned short r3 = (unsigned short)atomicAdd(&d_cnt[c.w], 1);
        ushort4 rr; rr.x = r0; rr.y = r1; rr.z = r2; rr.w = r3;
        reinterpret_cast<ushort4*>(d_rank)[t] = rr;
    }
    GBAR();   // 1

    // ---- Phase 2: per-chunk scan of padded counts ----
    __shared__ int sA[NTHR];
    {
        int node = blockIdx.x * CHUNK + tid;
        int v = 0;
        if (tid < CHUNK && node < NN) v = (d_cnt[node] + 3) & ~3;
        sA[tid] = v;
        __syncthreads();
        for (int off = 1; off < NTHR; off <<= 1) {
            int t2 = (tid >= off) ? sA[tid - off] : 0;
            __syncthreads();
            sA[tid] += t2;
            __syncthreads();
        }
        if (tid < CHUNK && node < NN) d_off[node] = sA[tid] - v;  // local excl
        if (tid == NTHR - 1) d_bsum2[blockIdx.x] = sA[NTHR - 1];
    }
    GBAR();   // 2

    // ---- Phase 3: block 0 scans the 592 chunk totals (exclusive) ----
    if (blockIdx.x == 0) {
        __shared__ int sB[NTHR];
        int vals[3]; int p = 0;
#pragma unroll
        for (int k = 0; k < 3; k++) {
            int idx = tid * 3 + k;
            vals[k] = (idx < NBLK) ? __ldcg(&d_bsum2[idx]) : 0;
            p += vals[k];
        }
        sB[tid] = p;
        __syncthreads();
        for (int off = 1; off < NTHR; off <<= 1) {
            int t2 = (tid >= off) ? sB[tid - off] : 0;
            __syncthreads();
            sB[tid] += t2;
            __syncthreads();
        }
        int run = sB[tid] - p;
#pragma unroll
        for (int k = 0; k < 3; k++) {
            int idx = tid * 3 + k;
            if (idx < NBLK) { d_bsum2[idx] = run; run += vals[k]; }
        }
    }
    GBAR();   // 3

    // ---- Phase 4: add chunk base, write pad records ----
    {
        int node = blockIdx.x * CHUNK + tid;
        if (tid < CHUNK && node < NN) {
            int base = __ldcg(&d_bsum2[blockIdx.x]);
            int o = d_off[node] + base;
            d_off[node] = o;
            int cnt = d_cnt[node];
            int cntp = (cnt + 3) & ~3;
            const unsigned int sent = ((unsigned int)SENT_ROW) << 15;
            for (int j = cnt; j < cntp; j++) d_csr[o + j] = sent;
        }
    }
    GBAR();   // 4

    // ---- Phase 5: fill (4 edges/iter) ----
    for (int t = gtid; t < EE / 4; t += TT) {
        int4 c = reinterpret_cast<const int4*>(col)[t];
        int4 r = reinterpret_cast<const int4*>(row)[t];
        float4 ww = reinterpret_cast<const float4*>(w)[t];
        ushort4 rk = reinterpret_cast<const ushort4*>(d_rank)[t];
        int o0 = d_off[c.x], o1 = d_off[c.y], o2 = d_off[c.z], o3 = d_off[c.w];
        unsigned int w0 = (unsigned int)__float2int_rn(ww.x * 32767.0f);
        unsigned int w1 = (unsigned int)__float2int_rn(ww.y * 32767.0f);
        unsigned int w2 = (unsigned int)__float2int_rn(ww.z * 32767.0f);
        unsigned int w3 = (unsigned int)__float2int_rn(ww.w * 32767.0f);
        d_csr[o0 + (int)rk.x] = (((unsigned int)r.x) << 15) | w0;
        d_csr[o1 + (int)rk.y] = (((unsigned int)r.y) << 15) | w1;
        d_csr[o2 + (int)rk.z] = (((unsigned int)r.z) << 15) | w2;
        d_csr[o3 + (int)rk.w] = (((unsigned int)r.w) << 15) | w3;
    }
    GBAR();   // 5

    // ---- Phase 6: weighted degree + h1pre = dis1*(x@W1) (16 lanes/node) ----
    __shared__ float sW1[7 * 16];
    if (tid < 7 * 16) sW1[tid] = W1[tid];
    __syncthreads();
    {
        int f = tid & 15;
        for (int g = (gtid >> 4); g < NN; g += (TT >> 4)) {
            if (g == 0) d_h1pre[NN * HH + f] = __float2half(0.0f);
            int start = d_off[g], cnt = d_cnt[g];
            float s = 0.0f;
            for (int j = f; j < cnt; j += 16)
                s += (float)(d_csr[start + j] & 32767u);
            s *= W_SCALE;
#pragma unroll
            for (int o = 8; o >= 1; o >>= 1) s += __shfl_xor_sync(0xffffffffu, s, o);
            float di1 = rsqrtf(s + 1.0f);
            if (f == 0) {
                d_dis1[g] = di1;
                d_dis2[g] = rsqrtf((float)cnt + 1.0f);
            }
            const float* xr = x + g * 7;
            float acc = 0.0f;
#pragma unroll
            for (int k = 0; k < 7; k++) acc += xr[k] * sW1[k * 16 + f];
            d_h1pre[(g << 4) + f] = __float2half(acc * di1);
        }
    }
    GBAR();   // 6

    // ---- Phase 7: GCN1 gather (2 lanes/node) ----
    {
        int qi = gtid & 1;
        const uint4* hp = reinterpret_cast<const uint4*>(d_h1pre);
        uint4* h1out = reinterpret_cast<uint4*>(d_h1);
        for (int g = (gtid >> 1); g < NN; g += (TT >> 1)) {
            if (g == 0) {
                uint4 ninf; ninf.x = ninf.y = ninf.z = ninf.w = 0xFC00FC00u;
                h1out[(NN << 1) + qi] = ninf;
            }
            int start = d_off[g];
            int nq = ((d_cnt[g] + 3) & ~3) >> 2;
            const uint4* rp = reinterpret_cast<const uint4*>(d_csr + start);
            float acc[8];
            h8_to_f8(hp[(g << 1) + qi], acc);
            int j = 0;
            for (; j + 2 <= nq; j += 2) {
                uint4 a = rp[j], b = rp[j + 1];
                fma_rec8(acc, a.x, hp, qi); fma_rec8(acc, a.y, hp, qi);
                fma_rec8(acc, a.z, hp, qi); fma_rec8(acc, a.w, hp, qi);
                fma_rec8(acc, b.x, hp, qi); fma_rec8(acc, b.y, hp, qi);
                fma_rec8(acc, b.z, hp, qi); fma_rec8(acc, b.w, hp, qi);
            }
            if (j < nq) {
                uint4 a = rp[j];
                fma_rec8(acc, a.x, hp, qi); fma_rec8(acc, a.y, hp, qi);
                fma_rec8(acc, a.z, hp, qi); fma_rec8(acc, a.w, hp, qi);
            }
            float di = d_dis1[g];
            uint4 outv;
            __half2* oh = reinterpret_cast<__half2*>(&outv);
#pragma unroll
            for (int m = 0; m < 4; m++) {
                float lo = acc[2 * m]     * di + b1[(qi << 3) + 2 * m];
                float hi = acc[2 * m + 1] * di + b1[(qi << 3) + 2 * m + 1];
                oh[m] = __floats2half2_rn(lo, hi);
            }
            h1out[(g << 1) + qi] = outv;
        }
    }
    GBAR();   // 7

    // ---- Phase 8: neighbor max pool + h2pre = dis2*(out2@W2) ----
    __shared__ float sW2[256];
    sW2[tid] = W2[tid];
    __syncthreads();
    {
        int qi = gtid & 1;
        const uint4* hp = reinterpret_cast<const uint4*>(d_h1);
        uint4* h2out = reinterpret_cast<uint4*>(d_h2pre);
        for (int g = (gtid >> 1); g < NN; g += (TT >> 1)) {
            if (g == 0) {
                uint4 z; z.x = z.y = z.z = z.w = 0u;
                h2out[(NN << 1) + qi] = z;
            }
            int start = d_off[g];
            int nq = ((d_cnt[g] + 3) & ~3) >> 2;
            const uint4* rp = reinterpret_cast<const uint4*>(d_csr + start);
            uint4 accv = hp[(g << 1) + qi];
            __half2* am = reinterpret_cast<__half2*>(&accv);
            int j = 0;
            for (; j + 2 <= nq; j += 2) {
                uint4 a = rp[j], b = rp[j + 1];
                max_rec8(am, a.x, hp, qi); max_rec8(am, a.y, hp, qi);
                max_rec8(am, a.z, hp, qi); max_rec8(am, a.w, hp, qi);
                max_rec8(am, b.x, hp, qi); max_rec8(am, b.y, hp, qi);
                max_rec8(am, b.z, hp, qi); max_rec8(am, b.w, hp, qi);
            }
            if (j < nq) {
                uint4 a = rp[j];
                max_rec8(am, a.x, hp, qi); max_rec8(am, a.y, hp, qi);
                max_rec8(am, a.z, hp, qi); max_rec8(am, a.w, hp, qi);
            }
            float o8[8];
            h8_to_f8(accv, o8);
            float4* o2p = reinterpret_cast<float4*>(d_out2);
            o2p[(g << 2) + (qi << 1) + 0] = make_float4(o8[0], o8[1], o8[2], o8[3]);
            o2p[(g << 2) + (qi << 1) + 1] = make_float4(o8[4], o8[5], o8[6], o8[7]);

            float oth[8];
#pragma unroll
            for (int k = 0; k < 8; k++) oth[k] = __shfl_xor_sync(0xffffffffu, o8[k], 1);
            float o16[16];
            if (qi == 0) {
#pragma unroll
                for (int k = 0; k < 8; k++) { o16[k] = o8[k]; o16[8 + k] = oth[k]; }
            } else {
#pragma unroll
                for (int k = 0; k < 8; k++) { o16[k] = oth[k]; o16[8 + k] = o8[k]; }
            }
            float di2 = d_dis2[g];
            uint4 outv;
            __half2* oh = reinterpret_cast<__half2*>(&outv);
#pragma unroll
            for (int m = 0; m < 4; m++) {
                float rv[2];
#pragma unroll
                for (int t2 = 0; t2 < 2; t2++) {
                    int f = (qi << 3) + 2 * m + t2;
                    float s = 0.0f;
#pragma unroll
                    for (int k = 0; k < 16; k++) s += o16[k] * sW2[k * 16 + f];
                    rv[t2] = s * di2;
                }
                oh[m] = __floats2half2_rn(rv[0], rv[1]);
            }
            h2out[(g << 1) + qi] = outv;
        }
    }
    GBAR();   // 8

    // ---- Phase 9: GCN2 gather + relu + global max pool (+cnt reset) ----
    {
        int qi = gtid & 1;
        const uint4* hp = reinterpret_cast<const uint4*>(d_h2pre);
        for (int g = (gtid >> 1); g < NN; g += (TT >> 1)) {
            int start = d_off[g];
            int nq = ((d_cnt[g] + 3) & ~3) >> 2;
            const uint4* rp = reinterpret_cast<const uint4*>(d_csr + start);
            float acc[8];
            h8_to_f8(hp[(g << 1) + qi], acc);
            int j = 0;
            for (; j + 2 <= nq; j += 2) {
                uint4 a = rp[j], b = rp[j + 1];
                sum_rec8(acc, a.x, hp, qi); sum_rec8(acc, a.y, hp, qi);
                sum_rec8(acc, a.z, hp, qi); sum_rec8(acc, a.w, hp, qi);
                sum_rec8(acc, b.x, hp, qi); sum_rec8(acc, b.y, hp, qi);
                sum_rec8(acc, b.z, hp, qi); sum_rec8(acc, b.w, hp, qi);
            }
            if (j < nq) {
                uint4 a = rp[j];
                sum_rec8(acc, a.x, hp, qi); sum_rec8(acc, a.y, hp, qi);
                sum_rec8(acc, a.z, hp, qi); sum_rec8(acc, a.w, hp, qi);
            }
            float di = d_dis2[g];
            const float4* o2p = reinterpret_cast<const float4*>(d_out2);
            float4 r0 = o2p[(g << 2) + (qi << 1) + 0];
            float4 r1 = o2p[(g << 2) + (qi << 1) + 1];
            float res[8] = {r0.x, r0.y, r0.z, r0.w, r1.x, r1.y, r1.z, r1.w};
            float* dst = &d_gmax[batch[g] * HH + (qi << 3)];
#pragma unroll
            for (int m = 0; m < 8; m++) {
                float h = fmaxf(res[m] + acc[m] * di + b2[(qi << 3) + m], 0.0f);
                if (h > dst[m]) atomic_max_float(dst + m, h);
            }
            if (qi == 0) d_cnt[g] = 0;
        }
    }
    GBAR();   // 9

    // ---- Phase 10: MLP on block 0 (one thread per graph) ----
    if (blockIdx.x == 0) {
        __shared__ float s1[256], s3[256], s4[16], sb1[16], sb3[16];
        __shared__ float sb4;
        int tx = tid;
        s1[tx] = Wl1[tx];
        s3[tx] = Wl3[tx];
        if (tx < 16) { s4[tx] = Wl4[tx]; sb1[tx] = bl1[tx]; sb3[tx] = bl3[tx]; }
        if (tx == 0) sb4 = bl4[0];
        __syncthreads();

        const float SLOPE = 0.22916666666666666f;
        float v[16], u[16];
#pragma unroll
        for (int f = 0; f < 16; f++) {
            v[f] = *((volatile float*)&d_gmax[tx * 16 + f]);  // bypass stale L1
            d_gmax[tx * 16 + f] = 0.0f;
        }
#pragma unroll
        for (int f = 0; f < 16; f++) {
            float s = sb1[f] + v[f];
#pragma unroll
            for (int k = 0; k < 16; k++) s += v[k] * s1[k * 16 + f];
            u[f] = (s >= 0.0f) ? s : SLOPE * s;
        }
#pragma unroll
        for (int f = 0; f < 16; f++) {
            float s = sb3[f] + u[f];
#pragma unroll
            for (int k = 0; k < 16; k++) s += u[k] * s3[k * 16 + f];
            v[f] = (s >= 0.0f) ? s : SLOPE * s;
        }
        float s = sb4;
#pragma unroll
        for (int k = 0; k < 16; k++) s += v[k] * s4[k];
        out[tx] = (s >= 0.0f) ? s : SLOPE * s;
    }
}

// ---------------------------------------------------------------------------

extern "C" void kernel_launch(void* const* d_in, const int* in_sizes, int n_in,
                              void* d_out, int out_size) {
    const float* x    = (const float*)d_in[0];
    const int*   ei   = (const int*)d_in[1];
    const int*   batch= (const int*)d_in[2];
    const float* ew   = (const float*)d_in[3];
    const float* W1   = (const float*)d_in[4];
    const float* b1   = (const float*)d_in[5];
    const float* W2   = (const float*)d_in[6];
    const float* b2   = (const float*)d_in[7];
    const float* Wl1  = (const float*)d_in[8];
    const float* bl1  = (const float*)d_in[9];
    const float* Wl3  = (const float*)d_in[10];
    const float* bl3  = (const float*)d_in[11];
    const float* Wl4  = (const float*)d_in[12];
    const float* bl4  = (const float*)d_in[13];
    const int* row = ei;         // edge_index[0]
    const int* col = ei + EE;    // edge_index[1]
    float* out = (float*)d_out;

    k_mega<<<NBLK, NTHR>>>(x, row, col, batch, ew, W1, b1, W2, b2,
                           Wl1, bl1, Wl3, bl3, Wl4, bl4, out);
}

// round 16
// speedup vs baseline: 1.1851x; 1.1851x over previous
#include <cuda_runtime.h>
#include <cuda_fp16.h>
#include <math_constants.h>

#define NN 100000
#define EE 3200000
#define GG 256
#define HH 16
#define NB_SCAN 98        // ceil(100000/1024)
#define CSR_CAP 3500032   // EE + 3*NN + slack (padded segments)
#define SENT_ROW NN       // sentinel row index for pad records

__device__ int   d_cnt[NN];        // zeroed by k_gather2 epilogue (static 0 first call)
__device__ float d_dis1[NN];
__device__ float d_dis2[NN];
__device__ int   d_off[NN];
__device__ __align__(16) unsigned short d_rank[EE];  // edge's rank within its col segment
__device__ int   d_bsum[128];
__device__ __align__(16) unsigned int d_csr[CSR_CAP];    // (row<<15) | w15
__device__ __align__(128) __half d_h1pre[(NN + 8) * HH]; // dis1[i]*(x@W1); row NN = 0
__device__ __align__(128) __half d_h1[(NN + 8) * HH];    // row NN = -inf
__device__ __align__(128) float  d_out2[NN * HH];        // fp32 residual
__device__ __align__(128) __half d_h2pre[(NN + 8) * HH]; // dis2[i]*(out2@W2); row NN = 0
__device__ float d_gmax[GG * HH];  // zeroed by k_mlp epilogue; relu>=0 so 0-seed valid

#define W_SCALE (1.0f / 32767.0f)

__device__ __forceinline__ void atomic_max_float(float* addr, float v) {
    if (v >= 0.0f) {
        atomicMax((int*)addr, __float_as_int(v));
    } else {
        atomicMin((unsigned int*)addr, __float_as_uint(v));
    }
}

// ---------------------------------------------------------------------------

// Count in-degree AND record each edge's rank: 2 edges per thread.
__global__ void k_count(const int* __restrict__ col) {
    int t = blockIdx.x * blockDim.x + threadIdx.x;
    if (t >= EE / 2) return;
    int2 c = reinterpret_cast<const int2*>(col)[t];
    unsigned short r0 = (unsigned short)atomicAdd(&d_cnt[c.x], 1);
    unsigned short r1 = (unsigned short)atomicAdd(&d_cnt[c.y], 1);
    ushort2 rr; rr.x = r0; rr.y = r1;
    reinterpret_cast<ushort2*>(d_rank)[t] = rr;
}

// Block-level exclusive scan of padded counts (1024 elems/block) + block sums.
__global__ void k_scan_blk() {
    __shared__ int s[256];
    int tid = threadIdx.x;
    int idx = blockIdx.x * 1024 + tid * 4;
    int v0 = (idx + 0 < NN) ? ((d_cnt[idx + 0] + 3) & ~3) : 0;
    int v1 = (idx + 1 < NN) ? ((d_cnt[idx + 1] + 3) & ~3) : 0;
    int v2 = (idx + 2 < NN) ? ((d_cnt[idx + 2] + 3) & ~3) : 0;
    int v3 = (idx + 3 < NN) ? ((d_cnt[idx + 3] + 3) & ~3) : 0;
    int local = v0 + v1 + v2 + v3;
    s[tid] = local;
    __syncthreads();
    for (int off = 1; off < 256; off <<= 1) {
        int t = (tid >= off) ? s[tid - off] : 0;
        __syncthreads();
        s[tid] += t;
        __syncthreads();
    }
    int excl = s[tid] - local;
    if (idx + 0 < NN) d_off[idx + 0] = excl;
    if (idx + 1 < NN) d_off[idx + 1] = excl + v0;
    if (idx + 2 < NN) d_off[idx + 2] = excl + v0 + v1;
    if (idx + 3 < NN) d_off[idx + 3] = excl + v0 + v1 + v2;
    if (tid == 255) d_bsum[blockIdx.x] = s[255];
}

// Finish scan: re-scan the 98 block sums in shared, add, and write pad records.
__global__ void k_scan_add() {
    __shared__ int s[128];
    __shared__ int se[128];
    int tid = threadIdx.x;
    int v = 0;
    if (tid < 128) {
        v = (tid < NB_SCAN) ? d_bsum[tid] : 0;
        s[tid] = v;
    }
    __syncthreads();
    for (int off = 1; off < 128; off <<= 1) {
        int t = (tid >= off && tid < 128) ? s[tid - off] : 0;
        __syncthreads();
        if (tid < 128) s[tid] += t;
        __syncthreads();
    }
    if (tid < 128) se[tid] = s[tid] - v;  // exclusive
    __syncthreads();
    int t = blockIdx.x * blockDim.x + tid;
    if (t >= NN) return;
    int o = d_off[t] + se[t >> 10];
    d_off[t] = o;
    int cnt = d_cnt[t];
    int cntp = (cnt + 3) & ~3;
    const unsigned int sent = ((unsigned int)SENT_ROW) << 15;  // w15 = 0
    for (int j = cnt; j < cntp; j++) d_csr[o + j] = sent;
}

// Atomic-free fill: 2 edges per thread; pos = off[col] + rank.
__global__ void k_fill(const int* __restrict__ row, const int* __restrict__ col,
                       const float* __restrict__ w) {
    int t = blockIdx.x * blockDim.x + threadIdx.x;
    if (t >= EE / 2) return;
    int2 c = reinterpret_cast<const int2*>(col)[t];
    int2 r = reinterpret_cast<const int2*>(row)[t];
    float2 ww = reinterpret_cast<const float2*>(w)[t];
    ushort2 rk = reinterpret_cast<const ushort2*>(d_rank)[t];
    int p0 = d_off[c.x] + (int)rk.x;
    int p1 = d_off[c.y] + (int)rk.y;
    unsigned int w0 = (unsigned int)__float2int_rn(ww.x * 32767.0f);
    unsigned int w1 = (unsigned int)__float2int_rn(ww.y * 32767.0f);
    d_csr[p0] = (((unsigned int)r.x) << 15) | w0;
    d_csr[p1] = (((unsigned int)r.y) << 15) | w1;
}

// Fused: weighted degree (4 lanes/node, uint4 records, shfl reduce) -> dis1/dis2;
// h1pre = dis1*(x@W1), 4 features per lane.
__global__ void __launch_bounds__(256) k_degpre1(const float* __restrict__ x,
                                                 const float* __restrict__ W1) {
    __shared__ float sW[7 * 16];
    if (threadIdx.x < 7 * 16) sW[threadIdx.x] = W1[threadIdx.x];
    __syncthreads();
    int g = blockIdx.x * 64 + (threadIdx.x >> 2);
    int qi = threadIdx.x & 3;
    if (g >= NN) return;   // 8 nodes/warp, NN % 8 == 0 -> warp-uniform exit
    if (g == 0) {          // sentinel row (4 halves per lane)
        __half zz[4] = {__float2half(0.0f), __float2half(0.0f),
                        __float2half(0.0f), __float2half(0.0f)};
        *reinterpret_cast<uint2*>(&d_h1pre[NN * HH + (qi << 2)]) =
            *reinterpret_cast<uint2*>(zz);
    }
    int start = d_off[g], cnt = d_cnt[g];
    int nq = ((cnt + 3) & ~3) >> 2;
    const uint4* rp = reinterpret_cast<const uint4*>(d_csr + start);
    float s = 0.0f;
    for (int j = qi; j < nq; j += 4) {
        uint4 a = rp[j];
        s += (float)(a.x & 32767u) + (float)(a.y & 32767u)
           + (float)(a.z & 32767u) + (float)(a.w & 32767u);
    }
    s *= W_SCALE;
    s += __shfl_xor_sync(0xffffffffu, s, 1);
    s += __shfl_xor_sync(0xffffffffu, s, 2);
    float di1 = rsqrtf(s + 1.0f);                  // + self-loop weight 1
    if (qi == 0) {
        d_dis1[g] = di1;
        d_dis2[g] = rsqrtf((float)cnt + 1.0f);
    }
    const float* xr = x + g * 7;
    float xv[7];
#pragma unroll
    for (int k = 0; k < 7; k++) xv[k] = xr[k];
    __half hv[4];
#pragma unroll
    for (int m = 0; m < 4; m++) {
        int f = (qi << 2) + m;
        float acc = 0.0f;
#pragma unroll
        for (int k = 0; k < 7; k++) acc += xv[k] * sW[k * 16 + f];
        hv[m] = __float2half(acc * di1);
    }
    *reinterpret_cast<uint2*>(&d_h1pre[(g << 4) + (qi << 2)]) =
        *reinterpret_cast<uint2*>(hv);
}

// Unpack a uint4 (8 halves) to 8 floats.
__device__ __forceinline__ void h8_to_f8(uint4 hv, float* o) {
    float2 f0 = __half22float2(*reinterpret_cast<__half2*>(&hv.x));
    float2 f1 = __half22float2(*reinterpret_cast<__half2*>(&hv.y));
    float2 f2 = __half22float2(*reinterpret_cast<__half2*>(&hv.z));
    float2 f3 = __half22float2(*reinterpret_cast<__half2*>(&hv.w));
    o[0] = f0.x; o[1] = f0.y; o[2] = f1.x; o[3] = f1.y;
    o[4] = f2.x; o[5] = f2.y; o[6] = f3.x; o[7] = f3.y;
}

__device__ __forceinline__ void fma_rec8(float* acc, unsigned int p,
                                         const uint4* __restrict__ hp, int qi) {
    int r = (int)(p >> 15);
    float w = (float)(p & 32767u) * W_SCALE;
    float v[8];
    h8_to_f8(hp[(r << 1) + qi], v);
#pragma unroll
    for (int m = 0; m < 8; m++) acc[m] = fmaf(w, v[m], acc[m]);
}

// GCN1 gather: 2 lanes/node, 8 features (uint4 of halves) per lane.
__global__ void __launch_bounds__(256) k_gather1(const float* __restrict__ b1) {
    int g = blockIdx.x * 128 + (threadIdx.x >> 1);
    int qi = threadIdx.x & 1;
    if (g >= NN) return;   // NN % 16 == 0 -> warp-uniform exit
    const uint4* hp = reinterpret_cast<const uint4*>(d_h1pre);
    uint4* h1out = reinterpret_cast<uint4*>(d_h1);
    if (g == 0) {   // sentinel row for maxpool: -inf halves
        uint4 ninf; ninf.x = ninf.y = ninf.z = ninf.w = 0xFC00FC00u;
        h1out[(NN << 1) + qi] = ninf;
    }
    int start = d_off[g];
    int nq = ((d_cnt[g] + 3) & ~3) >> 2;      // uint4 records
    const uint4* rp = reinterpret_cast<const uint4*>(d_csr + start);
    float acc[8];
    h8_to_f8(hp[(g << 1) + qi], acc);         // self loop
    int j = 0;
    for (; j + 2 <= nq; j += 2) {
        uint4 a = rp[j], b = rp[j + 1];
        fma_rec8(acc, a.x, hp, qi); fma_rec8(acc, a.y, hp, qi);
        fma_rec8(acc, a.z, hp, qi); fma_rec8(acc, a.w, hp, qi);
        fma_rec8(acc, b.x, hp, qi); fma_rec8(acc, b.y, hp, qi);
        fma_rec8(acc, b.z, hp, qi); fma_rec8(acc, b.w, hp, qi);
    }
    if (j < nq) {
        uint4 a = rp[j];
        fma_rec8(acc, a.x, hp, qi); fma_rec8(acc, a.y, hp, qi);
        fma_rec8(acc, a.z, hp, qi); fma_rec8(acc, a.w, hp, qi);
    }
    float di = d_dis1[g];
    uint4 outv;
    __half2* oh = reinterpret_cast<__half2*>(&outv);
#pragma unroll
    for (int m = 0; m < 4; m++) {
        float lo = acc[2 * m]     * di + b1[(qi << 3) + 2 * m];
        float hi = acc[2 * m + 1] * di + b1[(qi << 3) + 2 * m + 1];
        oh[m] = __floats2half2_rn(lo, hi);
    }
    h1out[(g << 1) + qi] = outv;
}

__device__ __forceinline__ void max_rec8(__half2* am, unsigned int p,
                                         const uint4* __restrict__ hp, int qi) {
    uint4 v = hp[((int)(p >> 15) << 1) + qi];
    __half2* vm = reinterpret_cast<__half2*>(&v);
    am[0] = __hmax2(am[0], vm[0]);
    am[1] = __hmax2(am[1], vm[1]);
    am[2] = __hmax2(am[2], vm[2]);
    am[3] = __hmax2(am[3], vm[3]);
}

// Fused: neighbor max pool (hmax2) + h2pre = dis2 * (out2 @ W2) via shfl pair.
__global__ void __launch_bounds__(256) k_gathermax_pre2(const float* __restrict__ W2) {
    __shared__ float sW[256];
    sW[threadIdx.x] = W2[threadIdx.x];
    __syncthreads();
    int g = blockIdx.x * 128 + (threadIdx.x >> 1);
    int qi = threadIdx.x & 1;
    if (g >= NN) return;   // NN % 16 == 0 -> warp-uniform exit
    const uint4* hp = reinterpret_cast<const uint4*>(d_h1);
    uint4* h2out = reinterpret_cast<uint4*>(d_h2pre);
    if (g == 0) {   // sentinel row for gather2 sum: 0
        uint4 z; z.x = z.y = z.z = z.w = 0u;
        h2out[(NN << 1) + qi] = z;
    }
    int start = d_off[g];
    int nq = ((d_cnt[g] + 3) & ~3) >> 2;
    const uint4* rp = reinterpret_cast<const uint4*>(d_csr + start);
    uint4 accv = hp[(g << 1) + qi];
    __half2* am = reinterpret_cast<__half2*>(&accv);
#pragma unroll 1
    for (int j = 0; j < nq; j++) {
        uint4 a = rp[j];
#pragma unroll
        for (int k = 0; k < 4; k++) {
            unsigned int p = (&a.x)[k];
            max_rec8(am, p, hp, qi);
        }
    }
    float o8[8];
    h8_to_f8(accv, o8);
    // out2 residual (fp32): two float4 stores per lane.
    float4* o2 = reinterpret_cast<float4*>(d_out2);
    o2[(g << 2) + (qi << 1) + 0] = make_float4(o8[0], o8[1], o8[2], o8[3]);
    o2[(g << 2) + (qi << 1) + 1] = make_float4(o8[4], o8[5], o8[6], o8[7]);

    // Assemble 16-feature row across the lane pair.
    float oth[8];
#pragma unroll
    for (int k = 0; k < 8; k++) oth[k] = __shfl_xor_sync(0xffffffffu, o8[k], 1);
    float o16[16];
    if (qi == 0) {
#pragma unroll
        for (int k = 0; k < 8; k++) { o16[k] = o8[k]; o16[8 + k] = oth[k]; }
    } else {
#pragma unroll
        for (int k = 0; k < 8; k++) { o16[k] = oth[k]; o16[8 + k] = o8[k]; }
    }
    float di2 = d_dis2[g];
    uint4 outv;
    __half2* oh = reinterpret_cast<__half2*>(&outv);
#pragma unroll
    for (int m = 0; m < 4; m++) {
        float r[2];
#pragma unroll
        for (int t = 0; t < 2; t++) {
            int f = (qi << 3) + 2 * m + t;
            float s = 0.0f;
#pragma unroll
            for (int k = 0; k < 16; k++) s += o16[k] * sW[k * 16 + f];
            r[t] = s * di2;
        }
        oh[m] = __floats2half2_rn(r[0], r[1]);
    }
    h2out[(g << 1) + qi] = outv;
}

// GCN2 gather (weights folded into h2pre) + fused relu + global max pool.
__global__ void __launch_bounds__(256) k_gather2(const int* __restrict__ batch,
                                                 const float* __restrict__ b2) {
    int g = blockIdx.x * 128 + (threadIdx.x >> 1);
    int qi = threadIdx.x & 1;
    if (g >= NN) return;
    int start = d_off[g];
    int nq = ((d_cnt[g] + 3) & ~3) >> 2;
    const uint4* rp = reinterpret_cast<const uint4*>(d_csr + start);
    const uint4* hp = reinterpret_cast<const uint4*>(d_h2pre);
    float acc[8];
    h8_to_f8(hp[(g << 1) + qi], acc);   // self loop
#pragma unroll 1
    for (int j = 0; j < nq; j++) {
        uint4 a = rp[j];
#pragma unroll
        for (int k = 0; k < 4; k++) {
            unsigned int p = (&a.x)[k];
            float v[8];
            h8_to_f8(hp[((int)(p >> 15) << 1) + qi], v);
#pragma unroll
            for (int m = 0; m < 8; m++) acc[m] += v[m];
        }
    }
    float di = d_dis2[g];
    const float4* o2 = reinterpret_cast<const float4*>(d_out2);
    float4 r0 = o2[(g << 2) + (qi << 1) + 0];
    float4 r1 = o2[(g << 2) + (qi << 1) + 1];
    float res[8] = {r0.x, r0.y, r0.z, r0.w, r1.x, r1.y, r1.z, r1.w};
    float* dst = &d_gmax[batch[g] * HH + (qi << 3)];
#pragma unroll
    for (int m = 0; m < 8; m++) {
        float h = fmaxf(res[m] + acc[m] * di + b2[(qi << 3) + m], 0.0f);
        if (h > dst[m]) atomic_max_float(dst + m, h);
    }
    if (qi == 0) d_cnt[g] = 0;   // self-clean for next replay
}

// Tiny residual MLP on [G, H]: one thread per graph. Epilogue resets d_gmax.
__global__ void k_mlp(const float* __restrict__ Wl1, const float* __restrict__ bl1,
                      const float* __restrict__ Wl3, const float* __restrict__ bl3,
                      const float* __restrict__ Wl4, const float* __restrict__ bl4,
                      float* __restrict__ out) {
    __shared__ float s1[256], s3[256], s4[16], sb1[16], sb3[16];
    __shared__ float sb4;
    int tx = threadIdx.x;
    s1[tx] = Wl1[tx];
    s3[tx] = Wl3[tx];
    if (tx < 16) { s4[tx] = Wl4[tx]; sb1[tx] = bl1[tx]; sb3[tx] = bl3[tx]; }
    if (tx == 0) sb4 = bl4[0];
    __syncthreads();

    const float SLOPE = 0.22916666666666666f;  // eval-mode RReLU mean slope
    float v[16], u[16];
#pragma unroll
    for (int f = 0; f < 16; f++) {
        v[f] = d_gmax[tx * 16 + f];
        d_gmax[tx * 16 + f] = 0.0f;   // self-clean (relu>=0 makes 0 a valid seed)
    }
#pragma unroll
    for (int f = 0; f < 16; f++) {
        float s = sb1[f] + v[f];
#pragma unroll
        for (int k = 0; k < 16; k++) s += v[k] * s1[k * 16 + f];
        u[f] = (s >= 0.0f) ? s : SLOPE * s;
    }
#pragma unroll
    for (int f = 0; f < 16; f++) {
        float s = sb3[f] + u[f];
#pragma unroll
        for (int k = 0; k < 16; k++) s += u[k] * s3[k * 16 + f];
        v[f] = (s >= 0.0f) ? s : SLOPE * s;
    }
    float s = sb4;
#pragma unroll
    for (int k = 0; k < 16; k++) s += v[k] * s4[k];
    out[tx] = (s >= 0.0f) ? s : SLOPE * s;
}

// ---------------------------------------------------------------------------

extern "C" void kernel_launch(void* const* d_in, const int* in_sizes, int n_in,
                              void* d_out, int out_size) {
    const float* x    = (const float*)d_in[0];
    const int*   ei   = (const int*)d_in[1];
    const int*   batch= (const int*)d_in[2];
    const float* ew   = (const float*)d_in[3];
    const float* W1   = (const float*)d_in[4];
    const float* b1   = (const float*)d_in[5];
    const float* W2   = (const float*)d_in[6];
    const float* b2   = (const float*)d_in[7];
    const float* Wl1  = (const float*)d_in[8];
    const float* bl1  = (const float*)d_in[9];
    const float* Wl3  = (const float*)d_in[10];
    const float* bl3  = (const float*)d_in[11];
    const float* Wl4  = (const float*)d_in[12];
    const float* bl4  = (const float*)d_in[13];
    const int* row = ei;         // edge_index[0]
    const int* col = ei + EE;    // edge_index[1]
    float* out = (float*)d_out;

    const int T = 256;
    k_count<<<(EE / 2 + T - 1) / T, T>>>(col);
    k_scan_blk<<<NB_SCAN, 256>>>();
    k_scan_add<<<(NN + T - 1) / T, T>>>();
    k_fill<<<(EE / 2 + T - 1) / T, T>>>(row, col, ew);
    k_degpre1<<<(NN + 63) / 64, 256>>>(x, W1);
    k_gather1<<<(NN + 127) / 128, 256>>>(b1);
    k_gathermax_pre2<<<(NN + 127) / 128, 256>>>(W2);
    k_gather2<<<(NN + 127) / 128, 256>>>(batch, b2);
    k_mlp<<<1, 256>>>(Wl1, bl1, Wl3, bl3, Wl4, bl4, out);
}